// round 1
// baseline (speedup 1.0000x reference)
#include <cuda_runtime.h>

#define BB 32
#define SS 8192
#define DD 64
#define FF 128
#define CS 128
#define NCHUNK (SS / CS)

// Scratch (device globals — no allocation allowed in kernel_launch)
__device__ float g_a [BB * SS * FF];   // k_s
__device__ float g_c [BB * SS * FF];   // k_s * v_f
__device__ float g_qs[BB * SS * FF];   // q_s
__device__ float g_pA[NCHUNK * BB * FF];
__device__ float g_pC[NCHUNK * BB * FF];

#define FMA4(acc, e, w0, w1, w2, w3)                                   \
    do {                                                               \
        acc.x = fmaf(e.x, w0.x, acc.x); acc.y = fmaf(e.x, w0.y, acc.y);\
        acc.z = fmaf(e.x, w0.z, acc.z); acc.w = fmaf(e.x, w0.w, acc.w);\
        acc.x = fmaf(e.y, w1.x, acc.x); acc.y = fmaf(e.y, w1.y, acc.y);\
        acc.z = fmaf(e.y, w1.z, acc.z); acc.w = fmaf(e.y, w1.w, acc.w);\
        acc.x = fmaf(e.z, w2.x, acc.x); acc.y = fmaf(e.z, w2.y, acc.y);\
        acc.z = fmaf(e.z, w2.z, acc.z); acc.w = fmaf(e.z, w2.w, acc.w);\
        acc.x = fmaf(e.w, w3.x, acc.x); acc.y = fmaf(e.w, w3.y, acc.y);\
        acc.z = fmaf(e.w, w3.z, acc.z); acc.w = fmaf(e.w, w3.w, acc.w);\
    } while (0)

// Kernel 1: features + spike gates.
// Tile: 16 s-rows x 128 f-cols per CTA, 128 threads, each thread does a
// 4s x 4f register tile for all three GEMMs (shares W loads across q/k/v).
__global__ __launch_bounds__(128) void featgate_kernel(
    const float* __restrict__ q, const float* __restrict__ k,
    const float* __restrict__ v, const float* __restrict__ w)
{
    __shared__ float sW[DD * FF];        // 32 KB
    __shared__ float sE[3][16][DD];      // 12 KB (exp'ed input rows)

    const int tid = threadIdx.x;
    const int b  = blockIdx.y;
    const int s0 = blockIdx.x * 16;

    // Load W (64x128) into smem
    {
        const float4* w4 = (const float4*)w;
        float4* sW4 = (float4*)sW;
#pragma unroll
        for (int i = 0; i < (DD * FF / 4) / 128; i++)   // 16 iters
            sW4[tid + i * 128] = w4[tid + i * 128];
    }

    // Load + exp the 16x64 input rows for q, k, v
    {
        const size_t base = ((size_t)b * SS + s0) * DD;
#pragma unroll
        for (int j = 0; j < 2; j++) {
            const int i   = tid + j * 128;     // float4 index, 0..255
            const int row = i >> 4;            // 16 float4 per 64-wide row
            const int col = (i & 15) * 4;
            float4 x;
            x = *(const float4*)&q[base + (size_t)row * DD + col];
            x.x = __expf(x.x); x.y = __expf(x.y); x.z = __expf(x.z); x.w = __expf(x.w);
            *(float4*)&sE[0][row][col] = x;
            x = *(const float4*)&k[base + (size_t)row * DD + col];
            x.x = __expf(x.x); x.y = __expf(x.y); x.z = __expf(x.z); x.w = __expf(x.w);
            *(float4*)&sE[1][row][col] = x;
            x = *(const float4*)&v[base + (size_t)row * DD + col];
            x.x = __expf(x.x); x.y = __expf(x.y); x.z = __expf(x.z); x.w = __expf(x.w);
            *(float4*)&sE[2][row][col] = x;
        }
    }
    __syncthreads();

    const int f4 = tid & 31;   // f-tile (4 cols each)
    const int s4 = tid >> 5;   // s-tile (4 rows each)

    float4 accQ[4], accK[4], accV[4];
#pragma unroll
    for (int r = 0; r < 4; r++) {
        accQ[r] = make_float4(0.f, 0.f, 0.f, 0.f);
        accK[r] = make_float4(0.f, 0.f, 0.f, 0.f);
        accV[r] = make_float4(0.f, 0.f, 0.f, 0.f);
    }

#pragma unroll 4
    for (int kk = 0; kk < DD; kk += 4) {
        const float4 w0 = *(const float4*)&sW[(kk + 0) * FF + f4 * 4];
        const float4 w1 = *(const float4*)&sW[(kk + 1) * FF + f4 * 4];
        const float4 w2 = *(const float4*)&sW[(kk + 2) * FF + f4 * 4];
        const float4 w3 = *(const float4*)&sW[(kk + 3) * FF + f4 * 4];
#pragma unroll
        for (int r = 0; r < 4; r++) {
            const int srow = s4 * 4 + r;
            float4 e;
            e = *(const float4*)&sE[0][srow][kk];
            FMA4(accQ[r], e, w0, w1, w2, w3);
            e = *(const float4*)&sE[1][srow][kk];
            FMA4(accK[r], e, w0, w1, w2, w3);
            e = *(const float4*)&sE[2][srow][kk];
            FMA4(accV[r], e, w0, w1, w2, w3);
        }
    }

    // Epilogue: gate + store a = k_s, c = k_s*v_f, qs = q_s
    const size_t obase = ((size_t)b * SS + s0 + s4 * 4) * FF + f4 * 4;
#pragma unroll
    for (int r = 0; r < 4; r++) {
        const float4 kf = accK[r], vf = accV[r], qf = accQ[r];
        float4 a, c, qs;
        a.x = (kf.x > 0.5f) ? kf.x : 0.f;  c.x = a.x * vf.x;
        a.y = (kf.y > 0.5f) ? kf.y : 0.f;  c.y = a.y * vf.y;
        a.z = (kf.z > 0.5f) ? kf.z : 0.f;  c.z = a.z * vf.z;
        a.w = (kf.w > 0.5f) ? kf.w : 0.f;  c.w = a.w * vf.w;
        qs.x = (qf.x > 0.5f) ? qf.x : 0.f;
        qs.y = (qf.y > 0.5f) ? qf.y : 0.f;
        qs.z = (qf.z > 0.5f) ? qf.z : 0.f;
        qs.w = (qf.w > 0.5f) ? qf.w : 0.f;
        const size_t o = obase + (size_t)r * FF;
        *(float4*)&g_a[o]  = a;
        *(float4*)&g_c[o]  = c;
        *(float4*)&g_qs[o] = qs;
    }
}

// Kernel 2: per-(lane, chunk) partial sums of a and c.
__global__ __launch_bounds__(128) void partial_kernel()
{
    const int f  = threadIdx.x;
    const int b  = blockIdx.y;
    const int ch = blockIdx.x;
    const size_t base = ((size_t)b * SS + (size_t)ch * CS) * FF + f;
    float a0 = 0.f, a1 = 0.f, c0 = 0.f, c1 = 0.f;
#pragma unroll 8
    for (int s = 0; s < CS; s += 2) {
        a0 += g_a[base + (size_t)(s + 0) * FF];
        a1 += g_a[base + (size_t)(s + 1) * FF];
        c0 += g_c[base + (size_t)(s + 0) * FF];
        c1 += g_c[base + (size_t)(s + 1) * FF];
    }
    g_pA[((size_t)ch * BB + b) * FF + f] = a0 + a1;
    g_pC[((size_t)ch * BB + b) * FF + f] = c0 + c1;
}

// Kernel 3: finalize — per-chunk prefix from partials, then in-chunk scan,
// attn ratio, multiply by q_s, write output.
__global__ __launch_bounds__(128) void finalize_kernel(float* __restrict__ out)
{
    const int f  = threadIdx.x;
    const int b  = blockIdx.y;
    const int ch = blockIdx.x;

    float cA = 0.f, cC = 0.f;
    for (int p = 0; p < ch; p++) {
        cA += g_pA[((size_t)p * BB + b) * FF + f];
        cC += g_pC[((size_t)p * BB + b) * FF + f];
    }

    const size_t base = ((size_t)b * SS + (size_t)ch * CS) * FF + f;
#pragma unroll 4
    for (int s = 0; s < CS; s++) {
        const size_t i = base + (size_t)s * FF;
        cA += g_a[i];
        cC += g_c[i];
        out[i] = g_qs[i] * __fdividef(cC + 1e-8f, cA + 1e-8f);
    }
}

extern "C" void kernel_launch(void* const* d_in, const int* in_sizes, int n_in,
                              void* d_out, int out_size)
{
    const float* q = (const float*)d_in[0];
    const float* k = (const float*)d_in[1];
    const float* v = (const float*)d_in[2];
    const float* w = (const float*)d_in[3];
    float* out = (float*)d_out;

    dim3 g1(SS / 16, BB);
    featgate_kernel<<<g1, 128>>>(q, k, v, w);

    dim3 g2(NCHUNK, BB);
    partial_kernel<<<g2, 128>>>();
    finalize_kernel<<<g2, 128>>>(out);
}